// round 13
// baseline (speedup 1.0000x reference)
#include <cuda_runtime.h>
#include <cuda_fp16.h>

#define NN 50000
#define EE 1600000
#define DD 128
#define HH 4
#define NEG 0.2f
#define SCAN_B ((NN + 1023) / 1024)   // 49 blocks

// ---------------- device scratch (static globals: allocation-free) ----------
__device__ __align__(16) __half g_xph[NN * DD];    // x @ W in fp16 (12.8 MB)
__device__ __align__(16) float g_asrc[NN * HH];    // per-node src attention
__device__ __align__(16) float g_adst[NN * HH];    // per-node dst attention
__device__ int   g_rowptr[NN];                     // exclusive CSR row pointers
__device__ int   g_rank[EE];                       // within-row rank of edge e
__device__ __align__(16) uint2 g_csr[EE];          // CSR: (src id, ew bits)
__device__ int   g_partial[SCAN_B];                // decoupled-scan partials
__device__ double g_ew_sum;
__device__ float g_mean_ew;
__device__ __align__(16) float g_coef[4];          // dot(W_edge_h, att_edge_h)
__device__ unsigned g_maxsrc[HH];                  // global per-head max (keyed)
__device__ int g_is64;                             // edge_index dtype flag

__device__ __forceinline__ float lrelu(float x) { return x > 0.f ? x : NEG * x; }
__device__ __forceinline__ float sel4(float4 v, int h) {
    return h == 0 ? v.x : (h == 1 ? v.y : (h == 2 ? v.z : v.w));
}
__device__ __forceinline__ unsigned fkey(float f) {
    unsigned u = __float_as_uint(f);
    return (u & 0x80000000u) ? ~u : (u | 0x80000000u);
}
__device__ __forceinline__ float funkey(unsigned k) {
    return __uint_as_float((k & 0x80000000u) ? (k ^ 0x80000000u) : ~k);
}

// ---------------- init: zero counters, detect int64 vs int32, coef ----------
__global__ void k_init(const int* __restrict__ ei_words,
                       const float* __restrict__ W_edge,
                       const float* __restrict__ att_edge) {
    int t = threadIdx.x;
    int gid = blockIdx.x * blockDim.x + t;
    if (gid < NN) g_rowptr[gid] = 0;
    if (gid < SCAN_B) g_partial[gid] = 0;
    if (gid == 0) g_ew_sum = 0.0;
    if (gid < HH) g_maxsrc[gid] = 0u;
    if (blockIdx.x == 0) {
        // int64 edge_index => high 32-bit words (odd positions) are all zero.
        int w = ei_words[2 * t + 1];
        int any = __syncthreads_or(w != 0);
        if (t == 0) g_is64 = (any == 0) ? 1 : 0;
        if (t < DD) {
            float p = W_edge[t] * att_edge[t];
            #pragma unroll
            for (int off = 16; off; off >>= 1)
                p += __shfl_xor_sync(0xffffffffu, p, off);
            if ((t & 31) == 0) g_coef[t >> 5] = p;
        }
    }
}

// ---------------- histogram + within-row rank + mean(edge_weight) -----------
__global__ void __launch_bounds__(256) k_histew(const void* __restrict__ ei,
                                                const float* __restrict__ ew) {
    __shared__ float ws[8];
    int e = blockIdx.x * 256 + threadIdx.x;
    float s = 0.f;
    if (e < EE) {
        int d = (g_is64 != 0) ? (int)((const long long*)ei)[EE + e]
                              : ((const int*)ei)[EE + e];
        int r = atomicAdd(&g_rowptr[d], 1);
        g_rank[e] = r;
        s = ew[e];
    }
    #pragma unroll
    for (int off = 16; off; off >>= 1) s += __shfl_xor_sync(~0u, s, off);
    int lane = threadIdx.x & 31, wd = threadIdx.x >> 5;
    if (lane == 0) ws[wd] = s;
    __syncthreads();
    if (wd == 0 && lane < 8) {
        s = ws[lane];
        #pragma unroll
        for (int off = 4; off; off >>= 1) s += __shfl_xor_sync(0xffu, s, off);
        if (lane == 0) atomicAdd(&g_ew_sum, (double)s);
    }
}

// ---------------- single-kernel exclusive scan (decoupled lookback) ---------
__global__ void __launch_bounds__(1024) k_scan() {
    __shared__ int wsum[32];
    __shared__ int s_off;
    int t = threadIdx.x, lane = t & 31, wd = t >> 5;
    int bid = blockIdx.x;
    int i = bid * 1024 + t;
    int v = (i < NN) ? g_rowptr[i] : 0;
    int x = v;
    #pragma unroll
    for (int off = 1; off < 32; off <<= 1) {
        int y = __shfl_up_sync(~0u, x, off);
        if (lane >= off) x += y;
    }
    if (lane == 31) wsum[wd] = x;
    __syncthreads();
    if (wd == 0) {
        int y = wsum[lane];
        #pragma unroll
        for (int off = 1; off < 32; off <<= 1) {
            int z = __shfl_up_sync(~0u, y, off);
            if (lane >= off) y += z;
        }
        wsum[lane] = y;
    }
    __syncthreads();
    int excl = (wd > 0 ? wsum[wd - 1] : 0) + x - v;
    int total = wsum[31];
    if (t == 0) atomicExch(&g_partial[bid], total + 1);  // 0 == not ready
    if (wd == 0) {
        int off = 0;
        for (int j = lane; j < bid; j += 32) {
            int p;
            do { p = atomicAdd(&g_partial[j], 0); } while (p == 0);
            off += p - 1;
        }
        #pragma unroll
        for (int o = 16; o; o >>= 1) off += __shfl_xor_sync(~0u, off, o);
        if (lane == 0) s_off = off;
    }
    __syncthreads();
    if (i < NN) g_rowptr[i] = excl + s_off;
    if (bid == 0 && t == 0) g_mean_ew = (float)(g_ew_sum / (double)EE);
}

// ---------------- scatter edges: ATOMIC-FREE (pos = rowptr[d] + rank[e]) ----
__global__ void __launch_bounds__(256) k_scatter(const void* __restrict__ ei,
                                                 const float* __restrict__ ew) {
    int e = blockIdx.x * 256 + threadIdx.x;
    if (e >= EE) return;
    int s, d;
    if (g_is64 != 0) {
        s = (int)((const long long*)ei)[e];
        d = (int)((const long long*)ei)[EE + e];
    } else {
        s = ((const int*)ei)[e];
        d = ((const int*)ei)[EE + e];
    }
    int pos = __ldg(&g_rowptr[d]) + g_rank[e];
    uint2 rec;
    rec.x = (unsigned)s;
    rec.y = __float_as_uint(ew[e]);
    g_csr[pos] = rec;
}

// ---------------- xp = x @ W  (32 rows x 128 cols per block) ----------------
__global__ void __launch_bounds__(256) k_gemm(const float* __restrict__ x,
                                              const float* __restrict__ W,
                                              const float* __restrict__ att_src,
                                              const float* __restrict__ att_dst) {
    __shared__ float sW[32][128];
    __shared__ float sx[32][36];
    __shared__ float smax[8][4];
    int t = threadIdx.x;
    int row0 = blockIdx.x * 32;
    int lane = t & 31, wd = t >> 5;
    int cc = lane * 4;
    int rr = wd * 4;
    int hd = lane >> 3;
    float acc[4][4] = {};
    for (int k0 = 0; k0 < 128; k0 += 32) {
        #pragma unroll
        for (int i = 0; i < 4; i++) {
            int w = t + i * 256;
            int kk = w >> 5;
            int c4 = (w & 31) * 4;
            *(float4*)&sW[kk][c4] = *(const float4*)&W[(k0 + kk) * 128 + c4];
        }
        {
            int r = t >> 3;
            int c4 = (t & 7) * 4;
            float4 xv = make_float4(0.f, 0.f, 0.f, 0.f);
            if (row0 + r < NN)
                xv = *(const float4*)&x[(row0 + r) * 128 + k0 + c4];
            *(float4*)&sx[r][c4] = xv;
        }
        __syncthreads();
        #pragma unroll
        for (int kk = 0; kk < 32; kk++) {
            float4 wv = *(const float4*)&sW[kk][cc];
            float xr0 = sx[rr + 0][kk], xr1 = sx[rr + 1][kk];
            float xr2 = sx[rr + 2][kk], xr3 = sx[rr + 3][kk];
            acc[0][0] += xr0 * wv.x; acc[0][1] += xr0 * wv.y;
            acc[0][2] += xr0 * wv.z; acc[0][3] += xr0 * wv.w;
            acc[1][0] += xr1 * wv.x; acc[1][1] += xr1 * wv.y;
            acc[1][2] += xr1 * wv.z; acc[1][3] += xr1 * wv.w;
            acc[2][0] += xr2 * wv.x; acc[2][1] += xr2 * wv.y;
            acc[2][2] += xr2 * wv.z; acc[2][3] += xr2 * wv.w;
            acc[3][0] += xr3 * wv.x; acc[3][1] += xr3 * wv.y;
            acc[3][2] += xr3 * wv.z; acc[3][3] += xr3 * wv.w;
        }
        __syncthreads();
    }
    float4 a4 = *(const float4*)&att_src[cc];
    float4 b4 = *(const float4*)&att_dst[cc];
    float wmax = -3.4e38f;
    #pragma unroll
    for (int q = 0; q < 4; q++) {
        int r = row0 + rr + q;
        float ps = acc[q][0] * a4.x + acc[q][1] * a4.y +
                   acc[q][2] * a4.z + acc[q][3] * a4.w;
        float pd = acc[q][0] * b4.x + acc[q][1] * b4.y +
                   acc[q][2] * b4.z + acc[q][3] * b4.w;
        #pragma unroll
        for (int off = 4; off; off >>= 1) {
            ps += __shfl_xor_sync(~0u, ps, off);
            pd += __shfl_xor_sync(~0u, pd, off);
        }
        if (r < NN) {
            if ((lane & 7) == 0) {
                g_asrc[r * 4 + hd] = ps;
                g_adst[r * 4 + hd] = pd;
            }
            __half2 h0 = __floats2half2_rn(acc[q][0], acc[q][1]);
            __half2 h1 = __floats2half2_rn(acc[q][2], acc[q][3]);
            uint2 u;
            u.x = *reinterpret_cast<unsigned*>(&h0);
            u.y = *reinterpret_cast<unsigned*>(&h1);
            *reinterpret_cast<uint2*>(&g_xph[r * 128 + cc]) = u;
            wmax = fmaxf(wmax, ps);
        }
    }
    if ((lane & 7) == 0) smax[wd][hd] = wmax;
    __syncthreads();
    if (t < HH) {
        float m = smax[0][t];
        #pragma unroll
        for (int w = 1; w < 8; w++) m = fmaxf(m, smax[w][t]);
        atomicMax(&g_maxsrc[t], fkey(m));
    }
}

// ---------------- fused softmax-aggregate + bias + LayerNorm + ELU ----------
// R12 structure; ONLY change: stage (w_h, src) as float2 per head so the
// phase-2 inner loop does ONE LDS.64 instead of two LDS.32 (agg is LSU-bound).
__global__ void __launch_bounds__(256, 6) k_agg(const float* __restrict__ bias,
                                                const float* __restrict__ gamma,
                                                const float* __restrict__ beta,
                                                float* __restrict__ out) {
    __shared__ float2 s_e[8][4][33];   // [warp][head][edge] = (w, src bits)
    int tid = threadIdx.x;
    int wslot = tid >> 5;
    int lane = tid & 31;
    int n = blockIdx.x * 8 + wslot;    // NN = 6250*8 exactly
    int hd = lane >> 3;
    const int cb = lane * 4;

    int row0 = g_rowptr[n];
    int row1 = (n == NN - 1) ? EE : g_rowptr[n + 1];
    float4 adst4 = *(const float4*)&g_adst[n * 4];
    float4 coef4 = *(const float4*)&g_coef[0];
    float4 M4;
    M4.x = lrelu(funkey(g_maxsrc[0]) + adst4.x + fmaxf(coef4.x, 0.f));
    M4.y = lrelu(funkey(g_maxsrc[1]) + adst4.y + fmaxf(coef4.y, 0.f));
    M4.z = lrelu(funkey(g_maxsrc[2]) + adst4.z + fmaxf(coef4.z, 0.f));
    M4.w = lrelu(funkey(g_maxsrc[3]) + adst4.w + fmaxf(coef4.w, 0.f));

    float4 dsum = make_float4(0.f, 0.f, 0.f, 0.f);
    float4 acc  = make_float4(0.f, 0.f, 0.f, 0.f);

    for (int base = row0; base < row1; base += 32) {
        int cnt = min(32, row1 - base);
        if (lane < cnt) {
            uint2 e = g_csr[base + lane];
            float srcf = __uint_as_float(e.x);
            float ewv = __uint_as_float(e.y);
            float4 a = *(const float4*)&g_asrc[(int)e.x * 4];
            float4 wv;
            wv.x = __expf(lrelu(a.x + adst4.x + ewv * coef4.x) - M4.x);
            wv.y = __expf(lrelu(a.y + adst4.y + ewv * coef4.y) - M4.y);
            wv.z = __expf(lrelu(a.z + adst4.z + ewv * coef4.z) - M4.z);
            wv.w = __expf(lrelu(a.w + adst4.w + ewv * coef4.w) - M4.w);
            dsum.x += wv.x; dsum.y += wv.y;
            dsum.z += wv.z; dsum.w += wv.w;
            s_e[wslot][0][lane] = make_float2(wv.x, srcf);
            s_e[wslot][1][lane] = make_float2(wv.y, srcf);
            s_e[wslot][2][lane] = make_float2(wv.z, srcf);
            s_e[wslot][3][lane] = make_float2(wv.w, srcf);
        }
        __syncwarp();
        #pragma unroll 4
        for (int k = 0; k < cnt; k++) {
            float2 p = s_e[wslot][hd][k];
            int s = (int)__float_as_uint(p.y);
            float w = p.x;
            uint2 hr = *reinterpret_cast<const uint2*>(&g_xph[s * 128 + cb]);
            float2 f0 = __half22float2(*reinterpret_cast<__half2*>(&hr.x));
            float2 f1 = __half22float2(*reinterpret_cast<__half2*>(&hr.y));
            acc.x += w * f0.x; acc.y += w * f0.y;
            acc.z += w * f1.x; acc.w += w * f1.y;
        }
        __syncwarp();
    }

    // reduce per-head denominators across the warp
    #pragma unroll
    for (int off = 16; off; off >>= 1) {
        dsum.x += __shfl_xor_sync(~0u, dsum.x, off);
        dsum.y += __shfl_xor_sync(~0u, dsum.y, off);
        dsum.z += __shfl_xor_sync(~0u, dsum.z, off);
        dsum.w += __shfl_xor_sync(~0u, dsum.w, off);
    }

    // self loop (edge_attr = mean of edge weights) — epilogue-only loads
    float4 asn4 = *(const float4*)&g_asrc[n * 4];
    float meanew = g_mean_ew;
    float4 ws4;
    ws4.x = __expf(lrelu(asn4.x + adst4.x + meanew * coef4.x) - M4.x);
    ws4.y = __expf(lrelu(asn4.y + adst4.y + meanew * coef4.y) - M4.y);
    ws4.z = __expf(lrelu(asn4.z + adst4.z + meanew * coef4.z) - M4.z);
    ws4.w = __expf(lrelu(asn4.w + adst4.w + meanew * coef4.w) - M4.w);
    {
        float w = sel4(ws4, hd);
        uint2 hr = *reinterpret_cast<const uint2*>(&g_xph[n * 128 + cb]);
        float2 f0 = __half22float2(*reinterpret_cast<__half2*>(&hr.x));
        float2 f1 = __half22float2(*reinterpret_cast<__half2*>(&hr.y));
        acc.x += w * f0.x; acc.y += w * f0.y;
        acc.z += w * f1.x; acc.w += w * f1.y;
    }
    float denom = sel4(dsum, hd) + sel4(ws4, hd);

    float inv = 1.f / (denom + 1e-16f);
    float4 b4 = *(const float4*)&bias[cb];
    float4 o;
    o.x = acc.x * inv + b4.x;
    o.y = acc.y * inv + b4.y;
    o.z = acc.z * inv + b4.z;
    o.w = acc.w * inv + b4.w;

    // LayerNorm over 128 channels (warp-wide)
    float s1 = o.x + o.y + o.z + o.w;
    float s2 = o.x * o.x + o.y * o.y + o.z * o.z + o.w * o.w;
    #pragma unroll
    for (int off = 16; off; off >>= 1) {
        s1 += __shfl_xor_sync(~0u, s1, off);
        s2 += __shfl_xor_sync(~0u, s2, off);
    }
    float mu = s1 * (1.f / 128.f);
    float var = s2 * (1.f / 128.f) - mu * mu;
    float rstd = rsqrtf(var + 1e-5f);
    float4 g4 = *(const float4*)&gamma[cb];
    float4 be4 = *(const float4*)&beta[cb];
    o.x = (o.x - mu) * rstd * g4.x + be4.x;
    o.y = (o.y - mu) * rstd * g4.y + be4.y;
    o.z = (o.z - mu) * rstd * g4.z + be4.z;
    o.w = (o.w - mu) * rstd * g4.w + be4.w;

    // ELU
    o.x = o.x > 0.f ? o.x : expm1f(o.x);
    o.y = o.y > 0.f ? o.y : expm1f(o.y);
    o.z = o.z > 0.f ? o.z : expm1f(o.z);
    o.w = o.w > 0.f ? o.w : expm1f(o.w);

    *(float4*)&out[n * 128 + cb] = o;
}

// ---------------- launch -----------------------------------------------------
static cudaStream_t g_side = nullptr;
static cudaEvent_t g_ev_fork = nullptr, g_ev_join = nullptr;

extern "C" void kernel_launch(void* const* d_in, const int* in_sizes, int n_in,
                              void* d_out, int out_size) {
    const float* x        = (const float*)d_in[0];
    const void*  ei       = d_in[1];
    const float* ew       = (const float*)d_in[2];
    const float* W        = (const float*)d_in[3];
    const float* att_src  = (const float*)d_in[4];
    const float* att_dst  = (const float*)d_in[5];
    const float* W_edge   = (const float*)d_in[6];
    const float* att_edge = (const float*)d_in[7];
    const float* bias     = (const float*)d_in[8];
    const float* gamma    = (const float*)d_in[9];
    const float* beta     = (const float*)d_in[10];
    float* out = (float*)d_out;

    if (g_side == nullptr) {  // one-time host-side resources (no device mem)
        cudaStreamCreateWithFlags(&g_side, cudaStreamNonBlocking);
        cudaEventCreateWithFlags(&g_ev_fork, cudaEventDisableTiming);
        cudaEventCreateWithFlags(&g_ev_join, cudaEventDisableTiming);
    }

    const int EB = (EE + 255) / 256;   // one edge per thread

    k_init<<<(NN + 255) / 256, 256>>>((const int*)ei, W_edge, att_edge);
    cudaEventRecord(g_ev_fork, 0);

    k_histew<<<EB, 256>>>(ei, ew);
    k_scan<<<SCAN_B, 1024>>>();
    k_scatter<<<EB, 256>>>(ei, ew);

    // GEMM on side stream: starts right after k_init, overlaps edge prep
    cudaStreamWaitEvent(g_side, g_ev_fork, 0);
    k_gemm<<<(NN + 31) / 32, 256, 0, g_side>>>(x, W, att_src, att_dst);
    cudaEventRecord(g_ev_join, g_side);

    cudaStreamWaitEvent(0, g_ev_join, 0);
    k_agg<<<(NN + 7) / 8, 256>>>(bias, gamma, beta, out);
}

// round 14
// speedup vs baseline: 1.1105x; 1.1105x over previous
#include <cuda_runtime.h>
#include <cuda_fp16.h>

#define NN 50000
#define EE 1600000
#define DD 128
#define HH 4
#define NEG 0.2f
#define SCAN_B ((NN + 1023) / 1024)   // 49 blocks

// ---------------- device scratch (static globals: allocation-free) ----------
__device__ __align__(16) __half g_xph[NN * DD];    // x @ W in fp16 (12.8 MB)
__device__ __align__(16) float g_asrc[NN * HH];    // per-node src attention
__device__ __align__(16) float g_adst[NN * HH];    // per-node dst attention
__device__ int   g_rowptr[NN];                     // exclusive CSR row pointers
__device__ unsigned g_dr[EE];                      // packed dst<<16 | rank
__device__ __align__(16) uint2 g_csr[EE];          // CSR: (src id, ew bits)
__device__ int   g_partial[SCAN_B];                // decoupled-scan partials
__device__ double g_ew_sum;
__device__ float g_mean_ew;
__device__ __align__(16) float g_coef[4];          // dot(W_edge_h, att_edge_h)
__device__ unsigned g_maxsrc[HH];                  // global per-head max (keyed)
__device__ int g_is64;                             // edge_index dtype flag

__device__ __forceinline__ float lrelu(float x) { return x > 0.f ? x : NEG * x; }
__device__ __forceinline__ float sel4(float4 v, int h) {
    return h == 0 ? v.x : (h == 1 ? v.y : (h == 2 ? v.z : v.w));
}
__device__ __forceinline__ unsigned fkey(float f) {
    unsigned u = __float_as_uint(f);
    return (u & 0x80000000u) ? ~u : (u | 0x80000000u);
}
__device__ __forceinline__ float funkey(unsigned k) {
    return __uint_as_float((k & 0x80000000u) ? (k ^ 0x80000000u) : ~k);
}

// ---------------- init: zero counters, detect int64 vs int32, coef ----------
__global__ void k_init(const int* __restrict__ ei_words,
                       const float* __restrict__ W_edge,
                       const float* __restrict__ att_edge) {
    int t = threadIdx.x;
    int gid = blockIdx.x * blockDim.x + t;
    if (gid < NN) g_rowptr[gid] = 0;
    if (gid < SCAN_B) g_partial[gid] = 0;
    if (gid == 0) g_ew_sum = 0.0;
    if (gid < HH) g_maxsrc[gid] = 0u;
    if (blockIdx.x == 0) {
        // int64 edge_index => high 32-bit words (odd positions) are all zero.
        int w = ei_words[2 * t + 1];
        int any = __syncthreads_or(w != 0);
        if (t == 0) g_is64 = (any == 0) ? 1 : 0;
        if (t < DD) {
            float p = W_edge[t] * att_edge[t];
            #pragma unroll
            for (int off = 16; off; off >>= 1)
                p += __shfl_xor_sync(0xffffffffu, p, off);
            if ((t & 31) == 0) g_coef[t >> 5] = p;
        }
    }
}

// ---------------- histogram + packed (dst,rank) + mean(edge_weight) ---------
// atomicAdd's return value is the edge's within-row rank; pack it with dst
// (both < 2^16) so the scatter never re-reads the dst half of edge_index.
__global__ void __launch_bounds__(256) k_histew(const void* __restrict__ ei,
                                                const float* __restrict__ ew) {
    __shared__ float ws[8];
    int e = blockIdx.x * 256 + threadIdx.x;
    float s = 0.f;
    if (e < EE) {
        int d = (g_is64 != 0) ? (int)((const long long*)ei)[EE + e]
                              : ((const int*)ei)[EE + e];
        int r = atomicAdd(&g_rowptr[d], 1);
        g_dr[e] = ((unsigned)d << 16) | (unsigned)r;
        s = ew[e];
    }
    #pragma unroll
    for (int off = 16; off; off >>= 1) s += __shfl_xor_sync(~0u, s, off);
    int lane = threadIdx.x & 31, wd = threadIdx.x >> 5;
    if (lane == 0) ws[wd] = s;
    __syncthreads();
    if (wd == 0 && lane < 8) {
        s = ws[lane];
        #pragma unroll
        for (int off = 4; off; off >>= 1) s += __shfl_xor_sync(0xffu, s, off);
        if (lane == 0) atomicAdd(&g_ew_sum, (double)s);
    }
}

// ---------------- single-kernel exclusive scan (decoupled lookback) ---------
__global__ void __launch_bounds__(1024) k_scan() {
    __shared__ int wsum[32];
    __shared__ int s_off;
    int t = threadIdx.x, lane = t & 31, wd = t >> 5;
    int bid = blockIdx.x;
    int i = bid * 1024 + t;
    int v = (i < NN) ? g_rowptr[i] : 0;
    int x = v;
    #pragma unroll
    for (int off = 1; off < 32; off <<= 1) {
        int y = __shfl_up_sync(~0u, x, off);
        if (lane >= off) x += y;
    }
    if (lane == 31) wsum[wd] = x;
    __syncthreads();
    if (wd == 0) {
        int y = wsum[lane];
        #pragma unroll
        for (int off = 1; off < 32; off <<= 1) {
            int z = __shfl_up_sync(~0u, y, off);
            if (lane >= off) y += z;
        }
        wsum[lane] = y;
    }
    __syncthreads();
    int excl = (wd > 0 ? wsum[wd - 1] : 0) + x - v;
    int total = wsum[31];
    if (t == 0) atomicExch(&g_partial[bid], total + 1);  // 0 == not ready
    if (wd == 0) {
        int off = 0;
        for (int j = lane; j < bid; j += 32) {
            int p;
            do { p = atomicAdd(&g_partial[j], 0); } while (p == 0);
            off += p - 1;
        }
        #pragma unroll
        for (int o = 16; o; o >>= 1) off += __shfl_xor_sync(~0u, off, o);
        if (lane == 0) s_off = off;
    }
    __syncthreads();
    if (i < NN) g_rowptr[i] = excl + s_off;
    if (bid == 0 && t == 0) g_mean_ew = (float)(g_ew_sum / (double)EE);
}

// ---------------- scatter: ATOMIC-FREE, dst never re-read -------------------
__global__ void __launch_bounds__(256) k_scatter(const void* __restrict__ ei,
                                                 const float* __restrict__ ew) {
    int e = blockIdx.x * 256 + threadIdx.x;
    if (e >= EE) return;
    int s = (g_is64 != 0) ? (int)((const long long*)ei)[e]
                          : ((const int*)ei)[e];
    unsigned dr = g_dr[e];
    int pos = __ldg(&g_rowptr[dr >> 16]) + (int)(dr & 0xffffu);
    uint2 rec;
    rec.x = (unsigned)s;
    rec.y = __float_as_uint(ew[e]);
    g_csr[pos] = rec;
}

// ---------------- xp = x @ W  (32 rows x 128 cols per block) ----------------
__global__ void __launch_bounds__(256) k_gemm(const float* __restrict__ x,
                                              const float* __restrict__ W,
                                              const float* __restrict__ att_src,
                                              const float* __restrict__ att_dst) {
    __shared__ float sW[32][128];
    __shared__ float sx[32][36];
    __shared__ float smax[8][4];
    int t = threadIdx.x;
    int row0 = blockIdx.x * 32;
    int lane = t & 31, wd = t >> 5;
    int cc = lane * 4;
    int rr = wd * 4;
    int hd = lane >> 3;
    float acc[4][4] = {};
    for (int k0 = 0; k0 < 128; k0 += 32) {
        #pragma unroll
        for (int i = 0; i < 4; i++) {
            int w = t + i * 256;
            int kk = w >> 5;
            int c4 = (w & 31) * 4;
            *(float4*)&sW[kk][c4] = *(const float4*)&W[(k0 + kk) * 128 + c4];
        }
        {
            int r = t >> 3;
            int c4 = (t & 7) * 4;
            float4 xv = make_float4(0.f, 0.f, 0.f, 0.f);
            if (row0 + r < NN)
                xv = *(const float4*)&x[(row0 + r) * 128 + k0 + c4];
            *(float4*)&sx[r][c4] = xv;
        }
        __syncthreads();
        #pragma unroll
        for (int kk = 0; kk < 32; kk++) {
            float4 wv = *(const float4*)&sW[kk][cc];
            float xr0 = sx[rr + 0][kk], xr1 = sx[rr + 1][kk];
            float xr2 = sx[rr + 2][kk], xr3 = sx[rr + 3][kk];
            acc[0][0] += xr0 * wv.x; acc[0][1] += xr0 * wv.y;
            acc[0][2] += xr0 * wv.z; acc[0][3] += xr0 * wv.w;
            acc[1][0] += xr1 * wv.x; acc[1][1] += xr1 * wv.y;
            acc[1][2] += xr1 * wv.z; acc[1][3] += xr1 * wv.w;
            acc[2][0] += xr2 * wv.x; acc[2][1] += xr2 * wv.y;
            acc[2][2] += xr2 * wv.z; acc[2][3] += xr2 * wv.w;
            acc[3][0] += xr3 * wv.x; acc[3][1] += xr3 * wv.y;
            acc[3][2] += xr3 * wv.z; acc[3][3] += xr3 * wv.w;
        }
        __syncthreads();
    }
    float4 a4 = *(const float4*)&att_src[cc];
    float4 b4 = *(const float4*)&att_dst[cc];
    float wmax = -3.4e38f;
    #pragma unroll
    for (int q = 0; q < 4; q++) {
        int r = row0 + rr + q;
        float ps = acc[q][0] * a4.x + acc[q][1] * a4.y +
                   acc[q][2] * a4.z + acc[q][3] * a4.w;
        float pd = acc[q][0] * b4.x + acc[q][1] * b4.y +
                   acc[q][2] * b4.z + acc[q][3] * b4.w;
        #pragma unroll
        for (int off = 4; off; off >>= 1) {
            ps += __shfl_xor_sync(~0u, ps, off);
            pd += __shfl_xor_sync(~0u, pd, off);
        }
        if (r < NN) {
            if ((lane & 7) == 0) {
                g_asrc[r * 4 + hd] = ps;
                g_adst[r * 4 + hd] = pd;
            }
            __half2 h0 = __floats2half2_rn(acc[q][0], acc[q][1]);
            __half2 h1 = __floats2half2_rn(acc[q][2], acc[q][3]);
            uint2 u;
            u.x = *reinterpret_cast<unsigned*>(&h0);
            u.y = *reinterpret_cast<unsigned*>(&h1);
            *reinterpret_cast<uint2*>(&g_xph[r * 128 + cc]) = u;
            wmax = fmaxf(wmax, ps);
        }
    }
    if ((lane & 7) == 0) smax[wd][hd] = wmax;
    __syncthreads();
    if (t < HH) {
        float m = smax[0][t];
        #pragma unroll
        for (int w = 1; w < 8; w++) m = fmaxf(m, smax[w][t]);
        atomicMax(&g_maxsrc[t], fkey(m));
    }
}

// ---------------- fused softmax-aggregate + bias + LayerNorm + ELU ----------
// (R12 winner, frozen)
__global__ void __launch_bounds__(256, 6) k_agg(const float* __restrict__ bias,
                                                const float* __restrict__ gamma,
                                                const float* __restrict__ beta,
                                                float* __restrict__ out) {
    __shared__ float4 s_w[8][32];
    __shared__ int    s_s[8][32];
    int tid = threadIdx.x;
    int wslot = tid >> 5;
    int lane = tid & 31;
    int n = blockIdx.x * 8 + wslot;    // NN = 6250*8 exactly
    int hd = lane >> 3;
    const int cb = lane * 4;

    int row0 = g_rowptr[n];
    int row1 = (n == NN - 1) ? EE : g_rowptr[n + 1];
    float4 adst4 = *(const float4*)&g_adst[n * 4];
    float4 coef4 = *(const float4*)&g_coef[0];
    float4 M4;
    M4.x = lrelu(funkey(g_maxsrc[0]) + adst4.x + fmaxf(coef4.x, 0.f));
    M4.y = lrelu(funkey(g_maxsrc[1]) + adst4.y + fmaxf(coef4.y, 0.f));
    M4.z = lrelu(funkey(g_maxsrc[2]) + adst4.z + fmaxf(coef4.z, 0.f));
    M4.w = lrelu(funkey(g_maxsrc[3]) + adst4.w + fmaxf(coef4.w, 0.f));

    float4 dsum = make_float4(0.f, 0.f, 0.f, 0.f);
    float4 acc  = make_float4(0.f, 0.f, 0.f, 0.f);

    for (int base = row0; base < row1; base += 32) {
        int cnt = min(32, row1 - base);
        float4 wv = make_float4(0.f, 0.f, 0.f, 0.f);
        int sm = 0;
        if (lane < cnt) {
            uint2 e = g_csr[base + lane];
            sm = (int)e.x;
            float ewv = __uint_as_float(e.y);
            float4 a = *(const float4*)&g_asrc[sm * 4];
            wv.x = __expf(lrelu(a.x + adst4.x + ewv * coef4.x) - M4.x);
            wv.y = __expf(lrelu(a.y + adst4.y + ewv * coef4.y) - M4.y);
            wv.z = __expf(lrelu(a.z + adst4.z + ewv * coef4.z) - M4.z);
            wv.w = __expf(lrelu(a.w + adst4.w + ewv * coef4.w) - M4.w);
            dsum.x += wv.x; dsum.y += wv.y;
            dsum.z += wv.z; dsum.w += wv.w;
        }
        s_w[wslot][lane] = wv;
        s_s[wslot][lane] = sm;
        __syncwarp();
        #pragma unroll 4
        for (int k = 0; k < cnt; k++) {
            int s = s_s[wslot][k];
            float w = ((const float*)&s_w[wslot][k])[hd];
            uint2 hr = *reinterpret_cast<const uint2*>(&g_xph[s * 128 + cb]);
            float2 f0 = __half22float2(*reinterpret_cast<__half2*>(&hr.x));
            float2 f1 = __half22float2(*reinterpret_cast<__half2*>(&hr.y));
            acc.x += w * f0.x; acc.y += w * f0.y;
            acc.z += w * f1.x; acc.w += w * f1.y;
        }
        __syncwarp();
    }

    // reduce per-head denominators across the warp
    #pragma unroll
    for (int off = 16; off; off >>= 1) {
        dsum.x += __shfl_xor_sync(~0u, dsum.x, off);
        dsum.y += __shfl_xor_sync(~0u, dsum.y, off);
        dsum.z += __shfl_xor_sync(~0u, dsum.z, off);
        dsum.w += __shfl_xor_sync(~0u, dsum.w, off);
    }

    // self loop (edge_attr = mean of edge weights) — epilogue-only loads
    float4 asn4 = *(const float4*)&g_asrc[n * 4];
    float meanew = g_mean_ew;
    float4 ws4;
    ws4.x = __expf(lrelu(asn4.x + adst4.x + meanew * coef4.x) - M4.x);
    ws4.y = __expf(lrelu(asn4.y + adst4.y + meanew * coef4.y) - M4.y);
    ws4.z = __expf(lrelu(asn4.z + adst4.z + meanew * coef4.z) - M4.z);
    ws4.w = __expf(lrelu(asn4.w + adst4.w + meanew * coef4.w) - M4.w);
    {
        float w = sel4(ws4, hd);
        uint2 hr = *reinterpret_cast<const uint2*>(&g_xph[n * 128 + cb]);
        float2 f0 = __half22float2(*reinterpret_cast<__half2*>(&hr.x));
        float2 f1 = __half22float2(*reinterpret_cast<__half2*>(&hr.y));
        acc.x += w * f0.x; acc.y += w * f0.y;
        acc.z += w * f1.x; acc.w += w * f1.y;
    }
    float denom = sel4(dsum, hd) + sel4(ws4, hd);

    float inv = 1.f / (denom + 1e-16f);
    float4 b4 = *(const float4*)&bias[cb];
    float4 o;
    o.x = acc.x * inv + b4.x;
    o.y = acc.y * inv + b4.y;
    o.z = acc.z * inv + b4.z;
    o.w = acc.w * inv + b4.w;

    // LayerNorm over 128 channels (warp-wide)
    float s1 = o.x + o.y + o.z + o.w;
    float s2 = o.x * o.x + o.y * o.y + o.z * o.z + o.w * o.w;
    #pragma unroll
    for (int off = 16; off; off >>= 1) {
        s1 += __shfl_xor_sync(~0u, s1, off);
        s2 += __shfl_xor_sync(~0u, s2, off);
    }
    float mu = s1 * (1.f / 128.f);
    float var = s2 * (1.f / 128.f) - mu * mu;
    float rstd = rsqrtf(var + 1e-5f);
    float4 g4 = *(const float4*)&gamma[cb];
    float4 be4 = *(const float4*)&beta[cb];
    o.x = (o.x - mu) * rstd * g4.x + be4.x;
    o.y = (o.y - mu) * rstd * g4.y + be4.y;
    o.z = (o.z - mu) * rstd * g4.z + be4.z;
    o.w = (o.w - mu) * rstd * g4.w + be4.w;

    // ELU
    o.x = o.x > 0.f ? o.x : expm1f(o.x);
    o.y = o.y > 0.f ? o.y : expm1f(o.y);
    o.z = o.z > 0.f ? o.z : expm1f(o.z);
    o.w = o.w > 0.f ? o.w : expm1f(o.w);

    *(float4*)&out[n * 128 + cb] = o;
}

// ---------------- launch -----------------------------------------------------
static cudaStream_t g_side = nullptr;
static cudaEvent_t g_ev_fork = nullptr, g_ev_join = nullptr;

extern "C" void kernel_launch(void* const* d_in, const int* in_sizes, int n_in,
                              void* d_out, int out_size) {
    const float* x        = (const float*)d_in[0];
    const void*  ei       = d_in[1];
    const float* ew       = (const float*)d_in[2];
    const float* W        = (const float*)d_in[3];
    const float* att_src  = (const float*)d_in[4];
    const float* att_dst  = (const float*)d_in[5];
    const float* W_edge   = (const float*)d_in[6];
    const float* att_edge = (const float*)d_in[7];
    const float* bias     = (const float*)d_in[8];
    const float* gamma    = (const float*)d_in[9];
    const float* beta     = (const float*)d_in[10];
    float* out = (float*)d_out;

    if (g_side == nullptr) {  // one-time host-side resources (no device mem)
        cudaStreamCreateWithFlags(&g_side, cudaStreamNonBlocking);
        cudaEventCreateWithFlags(&g_ev_fork, cudaEventDisableTiming);
        cudaEventCreateWithFlags(&g_ev_join, cudaEventDisableTiming);
    }

    const int EB = (EE + 255) / 256;   // one edge per thread

    // submission order puts k_gemm in ncu's slot 4 (stream semantics unchanged)
    k_init<<<(NN + 255) / 256, 256>>>((const int*)ei, W_edge, att_edge);
    cudaEventRecord(g_ev_fork, 0);

    k_histew<<<EB, 256>>>(ei, ew);
    k_scan<<<SCAN_B, 1024>>>();

    cudaStreamWaitEvent(g_side, g_ev_fork, 0);
    k_gemm<<<(NN + 31) / 32, 256, 0, g_side>>>(x, W, att_src, att_dst);
    cudaEventRecord(g_ev_join, g_side);

    k_scatter<<<EB, 256>>>(ei, ew);

    cudaStreamWaitEvent(0, g_ev_join, 0);
    k_agg<<<(NN + 7) / 8, 256>>>(bias, gamma, beta, out);
}

// round 15
// speedup vs baseline: 1.1121x; 1.0015x over previous
#include <cuda_runtime.h>
#include <cuda_fp16.h>

#define NN 50000
#define EE 1600000
#define DD 128
#define HH 4
#define NEG 0.2f
#define SCAN_B ((NN + 1023) / 1024)   // 49 blocks

// ---------------- device scratch (static globals: allocation-free) ----------
__device__ __align__(16) __half g_xph[NN * DD];    // x @ W in fp16 (12.8 MB)
__device__ __align__(16) float g_asrc[NN * HH];    // per-node src attention
__device__ __align__(16) float g_adst[NN * HH];    // per-node dst attention
__device__ int   g_rowptr[NN];                     // exclusive CSR row pointers
__device__ unsigned g_dr[EE];                      // packed dst<<16 | rank
__device__ __align__(16) uint2 g_csr[EE];          // CSR: (src id, ew bits)
__device__ int   g_partial[SCAN_B];                // decoupled-scan partials
__device__ double g_ew_sum;
__device__ float g_mean_ew;
__device__ __align__(16) float g_coef[4];          // dot(W_edge_h, att_edge_h)
__device__ unsigned g_maxsrc[HH];                  // global per-head max (keyed)
__device__ int g_is64;                             // edge_index dtype flag

__device__ __forceinline__ float lrelu(float x) { return x > 0.f ? x : NEG * x; }
__device__ __forceinline__ float sel4(float4 v, int h) {
    return h == 0 ? v.x : (h == 1 ? v.y : (h == 2 ? v.z : v.w));
}
__device__ __forceinline__ unsigned fkey(float f) {
    unsigned u = __float_as_uint(f);
    return (u & 0x80000000u) ? ~u : (u | 0x80000000u);
}
__device__ __forceinline__ float funkey(unsigned k) {
    return __uint_as_float((k & 0x80000000u) ? (k ^ 0x80000000u) : ~k);
}

// ---------------- init: zero counters, detect int64 vs int32, coef ----------
__global__ void k_init(const int* __restrict__ ei_words,
                       const float* __restrict__ W_edge,
                       const float* __restrict__ att_edge) {
    int t = threadIdx.x;
    int gid = blockIdx.x * blockDim.x + t;
    if (gid < NN) g_rowptr[gid] = 0;
    if (gid < SCAN_B) g_partial[gid] = 0;
    if (gid == 0) g_ew_sum = 0.0;
    if (gid < HH) g_maxsrc[gid] = 0u;
    if (blockIdx.x == 0) {
        // int64 edge_index => high 32-bit words (odd positions) are all zero.
        int w = ei_words[2 * t + 1];
        int any = __syncthreads_or(w != 0);
        if (t == 0) g_is64 = (any == 0) ? 1 : 0;
        if (t < DD) {
            float p = W_edge[t] * att_edge[t];
            #pragma unroll
            for (int off = 16; off; off >>= 1)
                p += __shfl_xor_sync(0xffffffffu, p, off);
            if ((t & 31) == 0) g_coef[t >> 5] = p;
        }
    }
}

// ---------------- histogram + packed (dst,rank) + mean(edge_weight) ---------
__global__ void __launch_bounds__(256) k_histew(const void* __restrict__ ei,
                                                const float* __restrict__ ew) {
    __shared__ float ws[8];
    int e = blockIdx.x * 256 + threadIdx.x;
    float s = 0.f;
    if (e < EE) {
        int d = (g_is64 != 0) ? (int)((const long long*)ei)[EE + e]
                              : ((const int*)ei)[EE + e];
        int r = atomicAdd(&g_rowptr[d], 1);
        g_dr[e] = ((unsigned)d << 16) | (unsigned)r;
        s = ew[e];
    }
    #pragma unroll
    for (int off = 16; off; off >>= 1) s += __shfl_xor_sync(~0u, s, off);
    int lane = threadIdx.x & 31, wd = threadIdx.x >> 5;
    if (lane == 0) ws[wd] = s;
    __syncthreads();
    if (wd == 0 && lane < 8) {
        s = ws[lane];
        #pragma unroll
        for (int off = 4; off; off >>= 1) s += __shfl_xor_sync(0xffu, s, off);
        if (lane == 0) atomicAdd(&g_ew_sum, (double)s);
    }
}

// ---------------- single-kernel exclusive scan (decoupled lookback) ---------
__global__ void __launch_bounds__(1024) k_scan() {
    __shared__ int wsum[32];
    __shared__ int s_off;
    int t = threadIdx.x, lane = t & 31, wd = t >> 5;
    int bid = blockIdx.x;
    int i = bid * 1024 + t;
    int v = (i < NN) ? g_rowptr[i] : 0;
    int x = v;
    #pragma unroll
    for (int off = 1; off < 32; off <<= 1) {
        int y = __shfl_up_sync(~0u, x, off);
        if (lane >= off) x += y;
    }
    if (lane == 31) wsum[wd] = x;
    __syncthreads();
    if (wd == 0) {
        int y = wsum[lane];
        #pragma unroll
        for (int off = 1; off < 32; off <<= 1) {
            int z = __shfl_up_sync(~0u, y, off);
            if (lane >= off) y += z;
        }
        wsum[lane] = y;
    }
    __syncthreads();
    int excl = (wd > 0 ? wsum[wd - 1] : 0) + x - v;
    int total = wsum[31];
    if (t == 0) atomicExch(&g_partial[bid], total + 1);  // 0 == not ready
    if (wd == 0) {
        int off = 0;
        for (int j = lane; j < bid; j += 32) {
            int p;
            do { p = atomicAdd(&g_partial[j], 0); } while (p == 0);
            off += p - 1;
        }
        #pragma unroll
        for (int o = 16; o; o >>= 1) off += __shfl_xor_sync(~0u, off, o);
        if (lane == 0) s_off = off;
    }
    __syncthreads();
    if (i < NN) g_rowptr[i] = excl + s_off;
    if (bid == 0 && t == 0) g_mean_ew = (float)(g_ew_sum / (double)EE);
}

// ---------------- scatter: ATOMIC-FREE, dst never re-read -------------------
__global__ void __launch_bounds__(256) k_scatter(const void* __restrict__ ei,
                                                 const float* __restrict__ ew) {
    int e = blockIdx.x * 256 + threadIdx.x;
    if (e >= EE) return;
    int s = (g_is64 != 0) ? (int)((const long long*)ei)[e]
                          : ((const int*)ei)[e];
    unsigned dr = g_dr[e];
    int pos = __ldg(&g_rowptr[dr >> 16]) + (int)(dr & 0xffffu);
    uint2 rec;
    rec.x = (unsigned)s;
    rec.y = __float_as_uint(ew[e]);
    g_csr[pos] = rec;
}

// ---------------- xp = x @ W  (32 rows x 128 cols per block) ----------------
// x tile stored TRANSPOSED in smem (sxT[kk][row]) so the inner loop reads the
// 4 row-values with ONE broadcast LDS.128 instead of 4 scalar LDS.32
// (gemm measured smem-wavefront bound: 8 -> 5 wavefronts per warp-kk).
__global__ void __launch_bounds__(256) k_gemm(const float* __restrict__ x,
                                              const float* __restrict__ W,
                                              const float* __restrict__ att_src,
                                              const float* __restrict__ att_dst) {
    __shared__ float sW[32][128];
    __shared__ float sxT[32][36];      // [kk][row]; 36*4=144B row, 16B aligned
    __shared__ float smax[8][4];
    int t = threadIdx.x;
    int row0 = blockIdx.x * 32;
    int lane = t & 31, wd = t >> 5;
    int cc = lane * 4;
    int rr = wd * 4;
    int hd = lane >> 3;
    float acc[4][4] = {};
    for (int k0 = 0; k0 < 128; k0 += 32) {
        #pragma unroll
        for (int i = 0; i < 4; i++) {
            int w = t + i * 256;
            int kk = w >> 5;
            int c4 = (w & 31) * 4;
            *(float4*)&sW[kk][c4] = *(const float4*)&W[(k0 + kk) * 128 + c4];
        }
        {
            int r = t >> 3;
            int c4 = (t & 7) * 4;
            float4 xv = make_float4(0.f, 0.f, 0.f, 0.f);
            if (row0 + r < NN)
                xv = *(const float4*)&x[(row0 + r) * 128 + k0 + c4];
            sxT[c4 + 0][r] = xv.x;
            sxT[c4 + 1][r] = xv.y;
            sxT[c4 + 2][r] = xv.z;
            sxT[c4 + 3][r] = xv.w;
        }
        __syncthreads();
        #pragma unroll
        for (int kk = 0; kk < 32; kk++) {
            float4 wv = *(const float4*)&sW[kk][cc];
            float4 xr = *(const float4*)&sxT[kk][rr];   // warp-broadcast
            acc[0][0] += xr.x * wv.x; acc[0][1] += xr.x * wv.y;
            acc[0][2] += xr.x * wv.z; acc[0][3] += xr.x * wv.w;
            acc[1][0] += xr.y * wv.x; acc[1][1] += xr.y * wv.y;
            acc[1][2] += xr.y * wv.z; acc[1][3] += xr.y * wv.w;
            acc[2][0] += xr.z * wv.x; acc[2][1] += xr.z * wv.y;
            acc[2][2] += xr.z * wv.z; acc[2][3] += xr.z * wv.w;
            acc[3][0] += xr.w * wv.x; acc[3][1] += xr.w * wv.y;
            acc[3][2] += xr.w * wv.z; acc[3][3] += xr.w * wv.w;
        }
        __syncthreads();
    }
    float4 a4 = *(const float4*)&att_src[cc];
    float4 b4 = *(const float4*)&att_dst[cc];
    float wmax = -3.4e38f;
    #pragma unroll
    for (int q = 0; q < 4; q++) {
        int r = row0 + rr + q;
        float ps = acc[q][0] * a4.x + acc[q][1] * a4.y +
                   acc[q][2] * a4.z + acc[q][3] * a4.w;
        float pd = acc[q][0] * b4.x + acc[q][1] * b4.y +
                   acc[q][2] * b4.z + acc[q][3] * b4.w;
        #pragma unroll
        for (int off = 4; off; off >>= 1) {
            ps += __shfl_xor_sync(~0u, ps, off);
            pd += __shfl_xor_sync(~0u, pd, off);
        }
        if (r < NN) {
            if ((lane & 7) == 0) {
                g_asrc[r * 4 + hd] = ps;
                g_adst[r * 4 + hd] = pd;
            }
            __half2 h0 = __floats2half2_rn(acc[q][0], acc[q][1]);
            __half2 h1 = __floats2half2_rn(acc[q][2], acc[q][3]);
            uint2 u;
            u.x = *reinterpret_cast<unsigned*>(&h0);
            u.y = *reinterpret_cast<unsigned*>(&h1);
            *reinterpret_cast<uint2*>(&g_xph[r * 128 + cc]) = u;
            wmax = fmaxf(wmax, ps);
        }
    }
    if ((lane & 7) == 0) smax[wd][hd] = wmax;
    __syncthreads();
    if (t < HH) {
        float m = smax[0][t];
        #pragma unroll
        for (int w = 1; w < 8; w++) m = fmaxf(m, smax[w][t]);
        atomicMax(&g_maxsrc[t], fkey(m));
    }
}

// ---------------- fused softmax-aggregate + bias + LayerNorm + ELU ----------
// (R12 winner, frozen)
__global__ void __launch_bounds__(256, 6) k_agg(const float* __restrict__ bias,
                                                const float* __restrict__ gamma,
                                                const float* __restrict__ beta,
                                                float* __restrict__ out) {
    __shared__ float4 s_w[8][32];
    __shared__ int    s_s[8][32];
    int tid = threadIdx.x;
    int wslot = tid >> 5;
    int lane = tid & 31;
    int n = blockIdx.x * 8 + wslot;    // NN = 6250*8 exactly
    int hd = lane >> 3;
    const int cb = lane * 4;

    int row0 = g_rowptr[n];
    int row1 = (n == NN - 1) ? EE : g_rowptr[n + 1];
    float4 adst4 = *(const float4*)&g_adst[n * 4];
    float4 coef4 = *(const float4*)&g_coef[0];
    float4 M4;
    M4.x = lrelu(funkey(g_maxsrc[0]) + adst4.x + fmaxf(coef4.x, 0.f));
    M4.y = lrelu(funkey(g_maxsrc[1]) + adst4.y + fmaxf(coef4.y, 0.f));
    M4.z = lrelu(funkey(g_maxsrc[2]) + adst4.z + fmaxf(coef4.z, 0.f));
    M4.w = lrelu(funkey(g_maxsrc[3]) + adst4.w + fmaxf(coef4.w, 0.f));

    float4 dsum = make_float4(0.f, 0.f, 0.f, 0.f);
    float4 acc  = make_float4(0.f, 0.f, 0.f, 0.f);

    for (int base = row0; base < row1; base += 32) {
        int cnt = min(32, row1 - base);
        float4 wv = make_float4(0.f, 0.f, 0.f, 0.f);
        int sm = 0;
        if (lane < cnt) {
            uint2 e = g_csr[base + lane];
            sm = (int)e.x;
            float ewv = __uint_as_float(e.y);
            float4 a = *(const float4*)&g_asrc[sm * 4];
            wv.x = __expf(lrelu(a.x + adst4.x + ewv * coef4.x) - M4.x);
            wv.y = __expf(lrelu(a.y + adst4.y + ewv * coef4.y) - M4.y);
            wv.z = __expf(lrelu(a.z + adst4.z + ewv * coef4.z) - M4.z);
            wv.w = __expf(lrelu(a.w + adst4.w + ewv * coef4.w) - M4.w);
            dsum.x += wv.x; dsum.y += wv.y;
            dsum.z += wv.z; dsum.w += wv.w;
        }
        s_w[wslot][lane] = wv;
        s_s[wslot][lane] = sm;
        __syncwarp();
        #pragma unroll 4
        for (int k = 0; k < cnt; k++) {
            int s = s_s[wslot][k];
            float w = ((const float*)&s_w[wslot][k])[hd];
            uint2 hr = *reinterpret_cast<const uint2*>(&g_xph[s * 128 + cb]);
            float2 f0 = __half22float2(*reinterpret_cast<__half2*>(&hr.x));
            float2 f1 = __half22float2(*reinterpret_cast<__half2*>(&hr.y));
            acc.x += w * f0.x; acc.y += w * f0.y;
            acc.z += w * f1.x; acc.w += w * f1.y;
        }
        __syncwarp();
    }

    // reduce per-head denominators across the warp
    #pragma unroll
    for (int off = 16; off; off >>= 1) {
        dsum.x += __shfl_xor_sync(~0u, dsum.x, off);
        dsum.y += __shfl_xor_sync(~0u, dsum.y, off);
        dsum.z += __shfl_xor_sync(~0u, dsum.z, off);
        dsum.w += __shfl_xor_sync(~0u, dsum.w, off);
    }

    // self loop (edge_attr = mean of edge weights) — epilogue-only loads
    float4 asn4 = *(const float4*)&g_asrc[n * 4];
    float meanew = g_mean_ew;
    float4 ws4;
    ws4.x = __expf(lrelu(asn4.x + adst4.x + meanew * coef4.x) - M4.x);
    ws4.y = __expf(lrelu(asn4.y + adst4.y + meanew * coef4.y) - M4.y);
    ws4.z = __expf(lrelu(asn4.z + adst4.z + meanew * coef4.z) - M4.z);
    ws4.w = __expf(lrelu(asn4.w + adst4.w + meanew * coef4.w) - M4.w);
    {
        float w = sel4(ws4, hd);
        uint2 hr = *reinterpret_cast<const uint2*>(&g_xph[n * 128 + cb]);
        float2 f0 = __half22float2(*reinterpret_cast<__half2*>(&hr.x));
        float2 f1 = __half22float2(*reinterpret_cast<__half2*>(&hr.y));
        acc.x += w * f0.x; acc.y += w * f0.y;
        acc.z += w * f1.x; acc.w += w * f1.y;
    }
    float denom = sel4(dsum, hd) + sel4(ws4, hd);

    float inv = 1.f / (denom + 1e-16f);
    float4 b4 = *(const float4*)&bias[cb];
    float4 o;
    o.x = acc.x * inv + b4.x;
    o.y = acc.y * inv + b4.y;
    o.z = acc.z * inv + b4.z;
    o.w = acc.w * inv + b4.w;

    // LayerNorm over 128 channels (warp-wide)
    float s1 = o.x + o.y + o.z + o.w;
    float s2 = o.x * o.x + o.y * o.y + o.z * o.z + o.w * o.w;
    #pragma unroll
    for (int off = 16; off; off >>= 1) {
        s1 += __shfl_xor_sync(~0u, s1, off);
        s2 += __shfl_xor_sync(~0u, s2, off);
    }
    float mu = s1 * (1.f / 128.f);
    float var = s2 * (1.f / 128.f) - mu * mu;
    float rstd = rsqrtf(var + 1e-5f);
    float4 g4 = *(const float4*)&gamma[cb];
    float4 be4 = *(const float4*)&beta[cb];
    o.x = (o.x - mu) * rstd * g4.x + be4.x;
    o.y = (o.y - mu) * rstd * g4.y + be4.y;
    o.z = (o.z - mu) * rstd * g4.z + be4.z;
    o.w = (o.w - mu) * rstd * g4.w + be4.w;

    // ELU
    o.x = o.x > 0.f ? o.x : expm1f(o.x);
    o.y = o.y > 0.f ? o.y : expm1f(o.y);
    o.z = o.z > 0.f ? o.z : expm1f(o.z);
    o.w = o.w > 0.f ? o.w : expm1f(o.w);

    *(float4*)&out[n * 128 + cb] = o;
}

// ---------------- launch -----------------------------------------------------
static cudaStream_t g_side = nullptr;
static cudaEvent_t g_ev_fork = nullptr, g_ev_join = nullptr;

extern "C" void kernel_launch(void* const* d_in, const int* in_sizes, int n_in,
                              void* d_out, int out_size) {
    const float* x        = (const float*)d_in[0];
    const void*  ei       = d_in[1];
    const float* ew       = (const float*)d_in[2];
    const float* W        = (const float*)d_in[3];
    const float* att_src  = (const float*)d_in[4];
    const float* att_dst  = (const float*)d_in[5];
    const float* W_edge   = (const float*)d_in[6];
    const float* att_edge = (const float*)d_in[7];
    const float* bias     = (const float*)d_in[8];
    const float* gamma    = (const float*)d_in[9];
    const float* beta     = (const float*)d_in[10];
    float* out = (float*)d_out;

    if (g_side == nullptr) {  // one-time host-side resources (no device mem)
        cudaStreamCreateWithFlags(&g_side, cudaStreamNonBlocking);
        cudaEventCreateWithFlags(&g_ev_fork, cudaEventDisableTiming);
        cudaEventCreateWithFlags(&g_ev_join, cudaEventDisableTiming);
    }

    const int EB = (EE + 255) / 256;   // one edge per thread

    // submission order keeps k_gemm in ncu's slot 4 (verify the smem fix)
    k_init<<<(NN + 255) / 256, 256>>>((const int*)ei, W_edge, att_edge);
    cudaEventRecord(g_ev_fork, 0);

    k_histew<<<EB, 256>>>(ei, ew);
    k_scan<<<SCAN_B, 1024>>>();

    cudaStreamWaitEvent(g_side, g_ev_fork, 0);
    k_gemm<<<(NN + 31) / 32, 256, 0, g_side>>>(x, W, att_src, att_dst);
    cudaEventRecord(g_ev_join, g_side);

    k_scatter<<<EB, 256>>>(ei, ew);

    cudaStreamWaitEvent(0, g_ev_join, 0);
    k_agg<<<(NN + 7) / 8, 256>>>(bias, gamma, beta, out);
}